// round 1
// baseline (speedup 1.0000x reference)
#include <cuda_runtime.h>
#include <math.h>

// LSTMCell fused (memory_version=6, time=2 -> memory cell pass-through path)
//   gates = [x|h] @ [W_ih;W_hh] + bias              (K=1024, N=2048)
//   s     = sigmoid([x|me] @ [W_memi;W_memh] + mb) * me   (K=2048, N=1536)
//   t     = s @ W_memt                               (K=1536, N=512)
//   c' = sig(f)*c + sig(i)*tanh(g) + t ; h' = sig(o)*tanh(c')
//   out_h = 0.8*h' + 0.2*h ; out_c = 0.8*c' + 0.2*c
// d_out = [h_next (B*512) | c_next (B*512)] fp32.

#define BATCH 16384
#define MASKV 0.8f

// scratch (no allocations allowed -> __device__ globals)
__device__ float g_gates[(size_t)BATCH * 2048];  // 128 MiB
__device__ float g_s[(size_t)BATCH * 1536];      //  96 MiB

__device__ __forceinline__ float sigf(float v) { return 1.0f / (1.0f + expf(-v)); }

// Classic 128x128x8 SGEMM, 256 threads, 8x8 per-thread tile.
// A = [A0 | A1] concatenated along K at K0 (row-major, strides lda0/lda1).
// W = [W0 ; W1] stacked along K at K0 (row-major, stride N).
// MODE 0: out -> g_gates (+bias)
// MODE 1: out -> g_s = sigmoid(acc+bias)*me
// MODE 2: A := g_s ; full LSTM epilogue -> d_out
template <int MODE>
__global__ void __launch_bounds__(256, 2) gemm_k(
    const float* __restrict__ A0, int lda0, int K0,
    const float* __restrict__ A1, int lda1, int K,
    const float* __restrict__ W0, const float* __restrict__ W1, int N,
    const float* __restrict__ bias,
    const float* __restrict__ me,
    const float* __restrict__ cin, const float* __restrict__ hin,
    float* __restrict__ out)
{
    __shared__ float As[8][128];  // transposed A tile: As[k][m]
    __shared__ float Bs[8][128];  // Bs[k][n]

    const int bm = blockIdx.y * 128;
    const int bn = blockIdx.x * 128;
    const int tid = threadIdx.x;
    const int tx = tid & 15;   // 16 column groups
    const int ty = tid >> 4;   // 16 row groups

    const float* a0p = (MODE == 2) ? (const float*)g_s : A0;
    const float* a1p = (MODE == 2) ? (const float*)g_s : A1;

    // A tile load mapping: 128 rows x 8 k -> 256 float4 (1/thread)
    const int a_row = tid >> 1;
    const int a_k4  = (tid & 1) * 4;
    // W tile load mapping: 8 rows x 128 cols -> 256 float4 (1/thread)
    const int b_row = tid >> 5;
    const int b_col = (tid & 31) * 4;

    float acc[8][8];
#pragma unroll
    for (int i = 0; i < 8; i++)
#pragma unroll
        for (int j = 0; j < 8; j++) acc[i][j] = 0.0f;

    for (int k0 = 0; k0 < K; k0 += 8) {
        // ---- stage A (choose source by K-split; K0 % 8 == 0 so no straddle)
        const int ka = k0 + a_k4;
        const float* ap = (ka < K0)
            ? a0p + (size_t)(bm + a_row) * lda0 + ka
            : a1p + (size_t)(bm + a_row) * lda1 + (ka - K0);
        const float4 av = *(const float4*)ap;
        As[a_k4 + 0][a_row] = av.x;
        As[a_k4 + 1][a_row] = av.y;
        As[a_k4 + 2][a_row] = av.z;
        As[a_k4 + 3][a_row] = av.w;

        // ---- stage W
        const int kb = k0 + b_row;
        const float* wp = (kb < K0)
            ? W0 + (size_t)kb * N + bn + b_col
            : W1 + (size_t)(kb - K0) * N + bn + b_col;
        *(float4*)&Bs[b_row][b_col] = *(const float4*)wp;

        __syncthreads();

#pragma unroll
        for (int k = 0; k < 8; k++) {
            const float4 a0v = *(const float4*)&As[k][ty * 8];
            const float4 a1v = *(const float4*)&As[k][ty * 8 + 4];
            const float4 b0v = *(const float4*)&Bs[k][tx * 8];
            const float4 b1v = *(const float4*)&Bs[k][tx * 8 + 4];
            const float ar[8] = {a0v.x, a0v.y, a0v.z, a0v.w, a1v.x, a1v.y, a1v.z, a1v.w};
            const float br[8] = {b0v.x, b0v.y, b0v.z, b0v.w, b1v.x, b1v.y, b1v.z, b1v.w};
#pragma unroll
            for (int i = 0; i < 8; i++)
#pragma unroll
                for (int j = 0; j < 8; j++)
                    acc[i][j] += ar[i] * br[j];
        }
        __syncthreads();
    }

    // ---- fused epilogues
#pragma unroll
    for (int i = 0; i < 8; i++) {
        const int r = bm + ty * 8 + i;
#pragma unroll
        for (int j = 0; j < 8; j++) {
            const int n = bn + tx * 8 + j;
            const float v = acc[i][j];
            if (MODE == 0) {
                g_gates[(size_t)r * 2048 + n] = v + bias[n];
            } else if (MODE == 1) {
                const float mg = v + bias[n];
                g_s[(size_t)r * 1536 + n] = sigf(mg) * me[(size_t)r * 1536 + n];
            } else {
                const size_t gbase = (size_t)r * 2048 + n;
                const float fg = g_gates[gbase];
                const float ig = g_gates[gbase + 512];
                const float og = g_gates[gbase + 1024];
                const float gg = g_gates[gbase + 1536];
                const float cv = cin[(size_t)r * 512 + n];
                const float hv = hin[(size_t)r * 512 + n];
                const float cn = sigf(fg) * cv + sigf(ig) * tanhf(gg) + v;
                const float hn = sigf(og) * tanhf(cn);
                out[(size_t)r * 512 + n] = hn * MASKV + hv * (1.0f - MASKV);
                out[(size_t)BATCH * 512 + (size_t)r * 512 + n] =
                    cn * MASKV + cv * (1.0f - MASKV);
            }
        }
    }
}

extern "C" void kernel_launch(void* const* d_in, const int* in_sizes, int n_in,
                              void* d_out, int out_size)
{
    const float* x       = (const float*)d_in[0];   // [B,512]
    const float* h       = (const float*)d_in[1];   // [B,512]
    const float* c       = (const float*)d_in[2];   // [B,512]
    const float* me      = (const float*)d_in[3];   // [B,1536]
    const float* W_ih    = (const float*)d_in[4];   // [512,2048]
    const float* W_hh    = (const float*)d_in[5];   // [512,2048]
    const float* bias    = (const float*)d_in[6];   // [2048]
    const float* W_memi  = (const float*)d_in[7];   // [512,1536]
    const float* W_memh  = (const float*)d_in[8];   // [1536,1536]
    const float* W_memt  = (const float*)d_in[9];   // [1536,512]
    const float* mem_b   = (const float*)d_in[10];  // [1536]
    // d_in[11] = time (unused: time=2 path is baked into the math)
    float* out = (float*)d_out;

    const dim3 blk(256);

    // gates = [x|h] @ [W_ih;W_hh] + bias
    gemm_k<0><<<dim3(2048 / 128, BATCH / 128), blk>>>(
        x, 512, 512, h, 512, 1024, W_ih, W_hh, 2048,
        bias, nullptr, nullptr, nullptr, nullptr);

    // s = sigmoid([x|me] @ [W_memi;W_memh] + mem_bias) * me
    gemm_k<1><<<dim3(1536 / 128, BATCH / 128), blk>>>(
        x, 512, 512, me, 1536, 2048, W_memi, W_memh, 1536,
        mem_b, me, nullptr, nullptr, nullptr);

    // t = s @ W_memt ; LSTM epilogue -> out
    gemm_k<2><<<dim3(512 / 128, BATCH / 128), blk>>>(
        nullptr, 1536, 1536, nullptr, 1536, 1536, W_memt, W_memt, 512,
        nullptr, nullptr, c, h, out);
}

// round 3
// speedup vs baseline: 2.7264x; 2.7264x over previous
#include <cuda_runtime.h>
#include <cstdint>
#include <math.h>

// LSTMCell fused via mma.sync tf32 (m16n8k8) GEMMs — compute_103-safe PTX.
//   gates = [x|h] @ Wt1^T + bias             (K=1024, N=2048)
//   s     = sigmoid([x|me] @ Wt2^T + mb)*me  (K=2048, N=1536)
//   t     = s @ Wt3^T ; LSTM epilogue        (K=1536, N=512)
// Weights pre-transposed to K-major [n][k] + rounded to tf32 (rna).

#define BATCH 16384

// ---------------- scratch (__device__ globals: no allocations allowed) ----
__device__ float g_gates[(size_t)BATCH * 2048];        // 128 MiB
__device__ float g_s[(size_t)BATCH * 1536];            //  96 MiB
__device__ float g_Wt1[(size_t)2048 * 1024];           // [n][k] K-major
__device__ float g_Wt2[(size_t)1536 * 2048];
__device__ float g_Wt3[(size_t)512 * 1536];

__device__ __forceinline__ float rna_tf32(float x) {
    float r; asm("cvt.rna.tf32.f32 %0, %1;" : "=f"(r) : "f"(x)); return r;
}
__device__ __forceinline__ float sigf(float x) { return 1.0f / (1.0f + __expf(-x)); }
__device__ __forceinline__ float tanh_(float x) { return 2.0f * sigf(2.0f * x) - 1.0f; }

__device__ __forceinline__ void mma_tf32(float& c0, float& c1, float& c2, float& c3,
                                         uint32_t a0, uint32_t a1, uint32_t a2, uint32_t a3,
                                         uint32_t b0, uint32_t b1) {
    asm volatile(
        "mma.sync.aligned.m16n8k8.row.col.f32.tf32.tf32.f32 "
        "{%0,%1,%2,%3}, {%4,%5,%6,%7}, {%8,%9}, {%0,%1,%2,%3};"
        : "+f"(c0), "+f"(c1), "+f"(c2), "+f"(c3)
        : "r"(a0), "r"(a1), "r"(a2), "r"(a3), "r"(b0), "r"(b1));
}

// ---------------- weight transpose + tf32 rounding pre-pass ---------------
__global__ void transpose_rna(const float* __restrict__ src, float* __restrict__ dst,
                              int R, int C, int dstStride) {
    __shared__ float t[32][33];
    const int c0 = blockIdx.x << 5, r0 = blockIdx.y << 5;
    const int tx = threadIdx.x, ty = threadIdx.y;
#pragma unroll
    for (int j = ty; j < 32; j += 8)
        t[j][tx] = rna_tf32(src[(size_t)(r0 + j) * C + c0 + tx]);
    __syncthreads();
#pragma unroll
    for (int j = ty; j < 32; j += 8)
        dst[(size_t)(c0 + j) * dstStride + r0 + tx] = t[tx][j];
}

// ---------------- main GEMM ------------------------------------------------
// Tile 128x128, BK=32, 8 warps (2M x 4N), each warp 64x32 = 4x4 m16n8k8.
// SMEM per stage: A[128][36] + B[128][36] floats (pad 36 -> conflict-free).
#define PAD 36
#define TILE_F (128 * PAD)                    // floats per tile
#define STAGE_B (2 * TILE_F * 4)              // bytes per stage (A+B)
#define SMEM_BYTES (2 * STAGE_B)              // double buffer = 147456... no: 2*36864=73728

template <int MODE>
__global__ void __launch_bounds__(256) mma_gemm(
    const float* __restrict__ A0, int lda0,
    const float* __restrict__ A1, int lda1,
    int K0, int K,
    const float* __restrict__ Wt,
    const float* __restrict__ bias,
    const float* __restrict__ me,
    const float* __restrict__ cin, const float* __restrict__ hin,
    float* __restrict__ outp)
{
    extern __shared__ float smem[];           // [2][2][TILE_F]  (stage, A/B)
    const int tid = threadIdx.x, wid = tid >> 5, lane = tid & 31;
    const int bm = blockIdx.y << 7, bn = blockIdx.x << 7;
    const int wm = (wid >> 2) << 6;           // 0 / 64
    const int wn = (wid & 3) << 5;            // 0/32/64/96
    const int grp = lane >> 2, qd = lane & 3;

    const float* as0 = (MODE == 2) ? (const float*)g_s : A0;
    const float* as1 = (MODE == 2) ? (const float*)g_s : A1;

    float acc[4][4][4];
#pragma unroll
    for (int mt = 0; mt < 4; mt++)
#pragma unroll
        for (int nt = 0; nt < 4; nt++)
#pragma unroll
            for (int q = 0; q < 4; q++) acc[mt][nt][q] = 0.0f;

    const int nst = K >> 5;
    float4 aR[4], bR[4];

    // staging map: i = tid + t*256 -> row = i>>3, q4 = (i&7)*4 (k within stage)
#define LDG_STAGE(S) do {                                                       \
    const int _k0 = (S) << 5;                                                   \
    _Pragma("unroll")                                                           \
    for (int t = 0; t < 4; t++) {                                               \
        const int i = tid + (t << 8);                                           \
        const int row = i >> 3, q4 = (i & 7) << 2;                              \
        const int ka = _k0 + q4;                                                \
        const float* pa = (ka < K0)                                             \
            ? as0 + (size_t)(bm + row) * lda0 + ka                              \
            : as1 + (size_t)(bm + row) * lda1 + (ka - K0);                      \
        aR[t] = *(const float4*)pa;                                             \
        bR[t] = *(const float4*)(Wt + (size_t)(bn + row) * K + _k0 + q4);       \
    } } while (0)

#define STS_STAGE(BUF) do {                                                     \
    float* dA = smem + (BUF) * 2 * TILE_F;                                      \
    float* dB = dA + TILE_F;                                                    \
    _Pragma("unroll")                                                           \
    for (int t = 0; t < 4; t++) {                                               \
        const int i = tid + (t << 8);                                           \
        const int off = (i >> 3) * PAD + ((i & 7) << 2);                        \
        float4 a = aR[t];                                                       \
        a.x = rna_tf32(a.x); a.y = rna_tf32(a.y);                               \
        a.z = rna_tf32(a.z); a.w = rna_tf32(a.w);                               \
        *(float4*)(dA + off) = a;                                               \
        *(float4*)(dB + off) = bR[t];                                           \
    } } while (0)

    LDG_STAGE(0);
    STS_STAGE(0);
    __syncthreads();

    for (int s = 0; s < nst; s++) {
        if (s + 1 < nst) LDG_STAGE(s + 1);

        const float* As = smem + (s & 1) * 2 * TILE_F;
        const float* Bs = As + TILE_F;
#pragma unroll
        for (int kk = 0; kk < 4; kk++) {
            const int kb = (kk << 3) + qd;
            uint32_t af[4][4];
#pragma unroll
            for (int mt = 0; mt < 4; mt++) {
                const int base = (wm + (mt << 4) + grp) * PAD + kb;
                af[mt][0] = __float_as_uint(As[base]);
                af[mt][1] = __float_as_uint(As[base + 8 * PAD]);
                af[mt][2] = __float_as_uint(As[base + 4]);
                af[mt][3] = __float_as_uint(As[base + 8 * PAD + 4]);
            }
            uint32_t bf[4][2];
#pragma unroll
            for (int nt = 0; nt < 4; nt++) {
                const int base = (wn + (nt << 3) + grp) * PAD + kb;
                bf[nt][0] = __float_as_uint(Bs[base]);
                bf[nt][1] = __float_as_uint(Bs[base + 4]);
            }
#pragma unroll
            for (int mt = 0; mt < 4; mt++)
#pragma unroll
                for (int nt = 0; nt < 4; nt++)
                    mma_tf32(acc[mt][nt][0], acc[mt][nt][1],
                             acc[mt][nt][2], acc[mt][nt][3],
                             af[mt][0], af[mt][1], af[mt][2], af[mt][3],
                             bf[nt][0], bf[nt][1]);
        }

        if (s + 1 < nst) {
            STS_STAGE((s + 1) & 1);
            __syncthreads();
        }
    }

    // ---- fused epilogues (c frag: c0,c1 @ (grp, qd*2) ; c2,c3 @ grp+8) ----
#pragma unroll
    for (int mt = 0; mt < 4; mt++) {
#pragma unroll
        for (int nt = 0; nt < 4; nt++) {
#pragma unroll
            for (int hrow = 0; hrow < 2; hrow++) {
                const int r = bm + wm + (mt << 4) + grp + (hrow << 3);
                const int cc = bn + wn + (nt << 3) + (qd << 1);
                const float v0 = acc[mt][nt][hrow * 2];
                const float v1 = acc[mt][nt][hrow * 2 + 1];
                if (MODE == 0) {
                    const float2 b2 = *(const float2*)(bias + cc);
                    float2 o = {v0 + b2.x, v1 + b2.y};
                    *(float2*)(g_gates + (size_t)r * 2048 + cc) = o;
                } else if (MODE == 1) {
                    const float2 b2 = *(const float2*)(bias + cc);
                    const float2 m2 = *(const float2*)(me + (size_t)r * 1536 + cc);
                    float2 o = {sigf(v0 + b2.x) * m2.x, sigf(v1 + b2.y) * m2.y};
                    *(float2*)(g_s + (size_t)r * 1536 + cc) = o;
                } else {
                    const size_t gb = (size_t)r * 2048 + cc;
                    const float2 f2 = *(const float2*)(g_gates + gb);
                    const float2 i2 = *(const float2*)(g_gates + gb + 512);
                    const float2 o2 = *(const float2*)(g_gates + gb + 1024);
                    const float2 g2 = *(const float2*)(g_gates + gb + 1536);
                    const float2 c2 = *(const float2*)(cin + (size_t)r * 512 + cc);
                    const float2 h2 = *(const float2*)(hin + (size_t)r * 512 + cc);
                    float2 oh, oc;
                    {
                        float cn = sigf(f2.x) * c2.x + sigf(i2.x) * tanh_(g2.x) + v0;
                        float hn = sigf(o2.x) * tanh_(cn);
                        oh.x = 0.8f * hn + 0.2f * h2.x;
                        oc.x = 0.8f * cn + 0.2f * c2.x;
                    }
                    {
                        float cn = sigf(f2.y) * c2.y + sigf(i2.y) * tanh_(g2.y) + v1;
                        float hn = sigf(o2.y) * tanh_(cn);
                        oh.y = 0.8f * hn + 0.2f * h2.y;
                        oc.y = 0.8f * cn + 0.2f * c2.y;
                    }
                    *(float2*)(outp + (size_t)r * 512 + cc) = oh;
                    *(float2*)(outp + (size_t)BATCH * 512 + (size_t)r * 512 + cc) = oc;
                }
            }
        }
    }
}

// ---------------- host ----------------------------------------------------
extern "C" void kernel_launch(void* const* d_in, const int* in_sizes, int n_in,
                              void* d_out, int out_size)
{
    const float* x      = (const float*)d_in[0];
    const float* h      = (const float*)d_in[1];
    const float* c      = (const float*)d_in[2];
    const float* me     = (const float*)d_in[3];
    const float* W_ih   = (const float*)d_in[4];
    const float* W_hh   = (const float*)d_in[5];
    const float* bias   = (const float*)d_in[6];
    const float* W_memi = (const float*)d_in[7];
    const float* W_memh = (const float*)d_in[8];
    const float* W_memt = (const float*)d_in[9];
    const float* mem_b  = (const float*)d_in[10];
    float* out = (float*)d_out;

    float *wt1, *wt2, *wt3;
    cudaGetSymbolAddress((void**)&wt1, g_Wt1);
    cudaGetSymbolAddress((void**)&wt2, g_Wt2);
    cudaGetSymbolAddress((void**)&wt3, g_Wt3);

    const int smem_bytes = 2 * 2 * TILE_F * 4;   // 73728
    cudaFuncSetAttribute(mma_gemm<0>, cudaFuncAttributeMaxDynamicSharedMemorySize, smem_bytes);
    cudaFuncSetAttribute(mma_gemm<1>, cudaFuncAttributeMaxDynamicSharedMemorySize, smem_bytes);
    cudaFuncSetAttribute(mma_gemm<2>, cudaFuncAttributeMaxDynamicSharedMemorySize, smem_bytes);

    const dim3 tb(32, 8);
    // Wt1[n][k]: k<512 from W_ih, k>=512 from W_hh   (rows n of length 1024)
    transpose_rna<<<dim3(64, 16), tb>>>(W_ih, wt1, 512, 2048, 1024);
    transpose_rna<<<dim3(64, 16), tb>>>(W_hh, wt1 + 512, 512, 2048, 1024);
    // Wt2[n][k]: k<512 W_memi, k>=512 W_memh         (rows of length 2048)
    transpose_rna<<<dim3(48, 16), tb>>>(W_memi, wt2, 512, 1536, 2048);
    transpose_rna<<<dim3(48, 48), tb>>>(W_memh, wt2 + 512, 1536, 1536, 2048);
    // Wt3[n][k] = W_memt^T                            (rows of length 1536)
    transpose_rna<<<dim3(16, 48), tb>>>(W_memt, wt3, 1536, 512, 1536);

    // gates = [x|h] @ Wt1^T + bias
    mma_gemm<0><<<dim3(16, 128), 256, smem_bytes>>>(
        x, 512, h, 512, 512, 1024, wt1, bias, nullptr, nullptr, nullptr, nullptr);

    // s = sigmoid([x|me] @ Wt2^T + mem_bias) * me
    mma_gemm<1><<<dim3(12, 128), 256, smem_bytes>>>(
        x, 512, me, 1536, 512, 2048, wt2, mem_b, me, nullptr, nullptr, nullptr);

    // t = s @ Wt3^T ; LSTM epilogue -> out
    mma_gemm<2><<<dim3(4, 128), 256, smem_bytes>>>(
        nullptr, 1536, nullptr, 1536, 1536, 1536, wt3, nullptr, nullptr, c, h, out);
}

// round 4
// speedup vs baseline: 3.6035x; 1.3217x over previous
#include <cuda_runtime.h>
#include <cstdint>
#include <math.h>

// LSTMCell fused via mma.sync tf32 (m16n8k8) GEMMs — compute_103-safe PTX.
//   gates = [x|h] @ Wt1^T + bias             (K=1024, N=2048)
//   s     = sigmoid([x|me] @ Wt2^T + mb)*me  (K=2048, N=1536)
//   t     = s @ Wt3^T ; LSTM epilogue        (K=1536, N=512)
// Weights pre-transposed to K-major [n][k] + tf32(rna). B tiles streamed with
// cp.async double-buffering; A tiles register-staged with rna rounding.

#define BATCH 16384

// ---------------- scratch (__device__ globals: no allocations allowed) ----
__device__ float g_gates[(size_t)BATCH * 2048];        // 128 MiB
__device__ float g_s[(size_t)BATCH * 1536];            //  96 MiB
__device__ float g_Wt1[(size_t)2048 * 1024];           // [n][k] K-major
__device__ float g_Wt2[(size_t)1536 * 2048];
__device__ float g_Wt3[(size_t)512 * 1536];

__device__ __forceinline__ float rna_tf32(float x) {
    float r; asm("cvt.rna.tf32.f32 %0, %1;" : "=f"(r) : "f"(x)); return r;
}
__device__ __forceinline__ float sigf(float x) { return 1.0f / (1.0f + __expf(-x)); }
__device__ __forceinline__ float tanh_(float x) { return 2.0f * sigf(2.0f * x) - 1.0f; }

__device__ __forceinline__ void mma_tf32(float& c0, float& c1, float& c2, float& c3,
                                         uint32_t a0, uint32_t a1, uint32_t a2, uint32_t a3,
                                         uint32_t b0, uint32_t b1) {
    asm volatile(
        "mma.sync.aligned.m16n8k8.row.col.f32.tf32.tf32.f32 "
        "{%0,%1,%2,%3}, {%4,%5,%6,%7}, {%8,%9}, {%0,%1,%2,%3};"
        : "+f"(c0), "+f"(c1), "+f"(c2), "+f"(c3)
        : "r"(a0), "r"(a1), "r"(a2), "r"(a3), "r"(b0), "r"(b1));
}

#define CP_ASYNC16(dst_u32, src_ptr) \
    asm volatile("cp.async.cg.shared.global [%0], [%1], 16;" \
                 :: "r"(dst_u32), "l"(src_ptr))
#define CP_COMMIT() asm volatile("cp.async.commit_group;")
#define CP_WAIT1()  asm volatile("cp.async.wait_group 1;" ::: "memory")
#define CP_WAIT0()  asm volatile("cp.async.wait_group 0;" ::: "memory")

// ---------------- weight transpose + tf32 rounding pre-pass ---------------
__global__ void transpose_rna(const float* __restrict__ src, float* __restrict__ dst,
                              int R, int C, int dstStride) {
    __shared__ float t[32][33];
    const int c0 = blockIdx.x << 5, r0 = blockIdx.y << 5;
    const int tx = threadIdx.x, ty = threadIdx.y;
#pragma unroll
    for (int j = ty; j < 32; j += 8)
        t[j][tx] = rna_tf32(src[(size_t)(r0 + j) * C + c0 + tx]);
    __syncthreads();
#pragma unroll
    for (int j = ty; j < 32; j += 8)
        dst[(size_t)(c0 + j) * dstStride + r0 + tx] = t[tx][j];
}

// ---------------- main GEMM ------------------------------------------------
// Tile 128x128, BK=32, 8 warps (2M x 4N), each warp 64x32 = 4x4 m16n8k8.
// SMEM per stage: A[128][36] + B[128][36] floats; double-buffered.
#define PAD 36
#define TILE_F (128 * PAD)
#define SMEM_BYTES (2 * 2 * TILE_F * 4)   // 73728

template <int MODE>
__global__ void __launch_bounds__(256, 2) mma_gemm(
    const float* __restrict__ A0, int lda0,
    const float* __restrict__ A1, int lda1,
    int K0, int K,
    const float* __restrict__ Wt,
    const float* __restrict__ bias,
    const float* __restrict__ me,
    const float* __restrict__ cin, const float* __restrict__ hin,
    float* __restrict__ outp)
{
    extern __shared__ float smem[];           // [2 buf][A|B][TILE_F]
    const uint32_t sbase = (uint32_t)__cvta_generic_to_shared(smem);
    const int tid = threadIdx.x, wid = tid >> 5, lane = tid & 31;
    const int bm = blockIdx.y << 7, bn = blockIdx.x << 7;
    const int wm = (wid >> 2) << 6;
    const int wn = (wid & 3) << 5;
    const int grp = lane >> 2, qd = lane & 3;

    const float* as0 = (MODE == 2) ? (const float*)g_s : A0;
    const float* as1 = (MODE == 2) ? (const float*)g_s : A1;

    float acc[4][4][4];
#pragma unroll
    for (int mt = 0; mt < 4; mt++)
#pragma unroll
        for (int nt = 0; nt < 4; nt++)
#pragma unroll
            for (int q = 0; q < 4; q++) acc[mt][nt][q] = 0.0f;

    const int nst = K >> 5;
    float4 aR[4];

    // staging map: i = tid + t*256 -> row = i>>3, q4 = (i&7)*4
#define LDG_A(S) do {                                                           \
    const int _k0 = (S) << 5;                                                   \
    _Pragma("unroll")                                                           \
    for (int t = 0; t < 4; t++) {                                               \
        const int i = tid + (t << 8);                                           \
        const int row = i >> 3, q4 = (i & 7) << 2;                              \
        const int ka = _k0 + q4;                                                \
        const float* pa = (ka < K0)                                             \
            ? as0 + (size_t)(bm + row) * lda0 + ka                              \
            : as1 + (size_t)(bm + row) * lda1 + (ka - K0);                      \
        aR[t] = *(const float4*)pa;                                             \
    } } while (0)

#define STS_A(BUF) do {                                                         \
    float* dA = smem + (BUF) * 2 * TILE_F;                                      \
    _Pragma("unroll")                                                           \
    for (int t = 0; t < 4; t++) {                                               \
        const int i = tid + (t << 8);                                           \
        const int off = (i >> 3) * PAD + ((i & 7) << 2);                        \
        float4 a = aR[t];                                                       \
        a.x = rna_tf32(a.x); a.y = rna_tf32(a.y);                               \
        a.z = rna_tf32(a.z); a.w = rna_tf32(a.w);                               \
        *(float4*)(dA + off) = a;                                               \
    } } while (0)

#define ISSUE_B(S, BUF) do {                                                    \
    const int _k0 = (S) << 5;                                                   \
    _Pragma("unroll")                                                           \
    for (int t = 0; t < 4; t++) {                                               \
        const int i = tid + (t << 8);                                           \
        const int row = i >> 3, q4 = (i & 7) << 2;                              \
        const uint32_t d = sbase +                                              \
            (uint32_t)(((BUF) * 2 * TILE_F + TILE_F + row * PAD + q4) << 2);    \
        CP_ASYNC16(d, Wt + (size_t)(bn + row) * K + _k0 + q4);                  \
    }                                                                           \
    CP_COMMIT(); } while (0)

    // prologue: fill both buffers
    LDG_A(0); STS_A(0); ISSUE_B(0, 0);
    LDG_A(1); STS_A(1); ISSUE_B(1, 1);

    for (int s = 0; s < nst; s++) {
        const int p = s & 1;
        if (s + 1 < nst) CP_WAIT1(); else CP_WAIT0();
        __syncthreads();
        if (s + 2 < nst) LDG_A(s + 2);

        const float* As = smem + p * 2 * TILE_F;
        const float* Bs = As + TILE_F;
#pragma unroll
        for (int kk = 0; kk < 4; kk++) {
            const int kb = (kk << 3) + qd;
            uint32_t af[4][4];
#pragma unroll
            for (int mt = 0; mt < 4; mt++) {
                const int base = (wm + (mt << 4) + grp) * PAD + kb;
                af[mt][0] = __float_as_uint(As[base]);
                af[mt][1] = __float_as_uint(As[base + 8 * PAD]);
                af[mt][2] = __float_as_uint(As[base + 4]);
                af[mt][3] = __float_as_uint(As[base + 8 * PAD + 4]);
            }
            uint32_t bf[4][2];
#pragma unroll
            for (int nt = 0; nt < 4; nt++) {
                const int base = (wn + (nt << 3) + grp) * PAD + kb;
                bf[nt][0] = __float_as_uint(Bs[base]);
                bf[nt][1] = __float_as_uint(Bs[base + 4]);
            }
#pragma unroll
            for (int mt = 0; mt < 4; mt++)
#pragma unroll
                for (int nt = 0; nt < 4; nt++)
                    mma_tf32(acc[mt][nt][0], acc[mt][nt][1],
                             acc[mt][nt][2], acc[mt][nt][3],
                             af[mt][0], af[mt][1], af[mt][2], af[mt][3],
                             bf[nt][0], bf[nt][1]);
        }

        __syncthreads();
        if (s + 2 < nst) { STS_A((s + 2) & 1); ISSUE_B(s + 2, p); }
    }

    // ---- fused epilogues (c frag rows grp/grp+8, cols 2qd/2qd+1) ----
#pragma unroll
    for (int mt = 0; mt < 4; mt++) {
#pragma unroll
        for (int nt = 0; nt < 4; nt++) {
#pragma unroll
            for (int hrow = 0; hrow < 2; hrow++) {
                const int r = bm + wm + (mt << 4) + grp + (hrow << 3);
                const int cc = bn + wn + (nt << 3) + (qd << 1);
                const float v0 = acc[mt][nt][hrow * 2];
                const float v1 = acc[mt][nt][hrow * 2 + 1];
                if (MODE == 0) {
                    const float2 b2 = *(const float2*)(bias + cc);
                    float2 o = {v0 + b2.x, v1 + b2.y};
                    *(float2*)(g_gates + (size_t)r * 2048 + cc) = o;
                } else if (MODE == 1) {
                    const float2 b2 = *(const float2*)(bias + cc);
                    const float2 m2 = *(const float2*)(me + (size_t)r * 1536 + cc);
                    float2 o = {sigf(v0 + b2.x) * m2.x, sigf(v1 + b2.y) * m2.y};
                    *(float2*)(g_s + (size_t)r * 1536 + cc) = o;
                } else {
                    const size_t gb = (size_t)r * 2048 + cc;
                    const float2 f2 = *(const float2*)(g_gates + gb);
                    const float2 i2 = *(const float2*)(g_gates + gb + 512);
                    const float2 o2 = *(const float2*)(g_gates + gb + 1024);
                    const float2 g2 = *(const float2*)(g_gates + gb + 1536);
                    const float2 c2 = *(const float2*)(cin + (size_t)r * 512 + cc);
                    const float2 h2 = *(const float2*)(hin + (size_t)r * 512 + cc);
                    float2 oh, oc;
                    {
                        float cn = sigf(f2.x) * c2.x + sigf(i2.x) * tanh_(g2.x) + v0;
                        float hn = sigf(o2.x) * tanh_(cn);
                        oh.x = 0.8f * hn + 0.2f * h2.x;
                        oc.x = 0.8f * cn + 0.2f * c2.x;
                    }
                    {
                        float cn = sigf(f2.y) * c2.y + sigf(i2.y) * tanh_(g2.y) + v1;
                        float hn = sigf(o2.y) * tanh_(cn);
                        oh.y = 0.8f * hn + 0.2f * h2.y;
                        oc.y = 0.8f * cn + 0.2f * c2.y;
                    }
                    *(float2*)(outp + (size_t)r * 512 + cc) = oh;
                    *(float2*)(outp + (size_t)BATCH * 512 + (size_t)r * 512 + cc) = oc;
                }
            }
        }
    }
}

// ---------------- host ----------------------------------------------------
extern "C" void kernel_launch(void* const* d_in, const int* in_sizes, int n_in,
                              void* d_out, int out_size)
{
    const float* x      = (const float*)d_in[0];
    const float* h      = (const float*)d_in[1];
    const float* c      = (const float*)d_in[2];
    const float* me     = (const float*)d_in[3];
    const float* W_ih   = (const float*)d_in[4];
    const float* W_hh   = (const float*)d_in[5];
    const float* bias   = (const float*)d_in[6];
    const float* W_memi = (const float*)d_in[7];
    const float* W_memh = (const float*)d_in[8];
    const float* W_memt = (const float*)d_in[9];
    const float* mem_b  = (const float*)d_in[10];
    float* out = (float*)d_out;

    float *wt1, *wt2, *wt3;
    cudaGetSymbolAddress((void**)&wt1, g_Wt1);
    cudaGetSymbolAddress((void**)&wt2, g_Wt2);
    cudaGetSymbolAddress((void**)&wt3, g_Wt3);

    cudaFuncSetAttribute(mma_gemm<0>, cudaFuncAttributeMaxDynamicSharedMemorySize, SMEM_BYTES);
    cudaFuncSetAttribute(mma_gemm<1>, cudaFuncAttributeMaxDynamicSharedMemorySize, SMEM_BYTES);
    cudaFuncSetAttribute(mma_gemm<2>, cudaFuncAttributeMaxDynamicSharedMemorySize, SMEM_BYTES);

    const dim3 tb(32, 8);
    transpose_rna<<<dim3(64, 16), tb>>>(W_ih, wt1, 512, 2048, 1024);
    transpose_rna<<<dim3(64, 16), tb>>>(W_hh, wt1 + 512, 512, 2048, 1024);
    transpose_rna<<<dim3(48, 16), tb>>>(W_memi, wt2, 512, 1536, 2048);
    transpose_rna<<<dim3(48, 48), tb>>>(W_memh, wt2 + 512, 1536, 1536, 2048);
    transpose_rna<<<dim3(16, 48), tb>>>(W_memt, wt3, 1536, 512, 1536);

    mma_gemm<0><<<dim3(16, 128), 256, SMEM_BYTES>>>(
        x, 512, h, 512, 512, 1024, wt1, bias, nullptr, nullptr, nullptr, nullptr);

    mma_gemm<1><<<dim3(12, 128), 256, SMEM_BYTES>>>(
        x, 512, me, 1536, 512, 2048, wt2, mem_b, me, nullptr, nullptr, nullptr);

    mma_gemm<2><<<dim3(4, 128), 256, SMEM_BYTES>>>(
        nullptr, 1536, nullptr, 1536, 1536, 1536, wt3, nullptr, nullptr, c, h, out);
}